// round 16
// baseline (speedup 1.0000x reference)
#include <cuda_runtime.h>
#include <math.h>
#include <stdint.h>

#define FRAME_LEN 400
#define HOP       160
#define NFFT      512
#define NBINS     257
#define NMEL      80
#define NFRAMES   2998
#define NSAMP     480000
#define BATCH     32
#define PREEMPH   0.97f
#define MEL_FLOOR 1.192092955078125e-07f
#define FPB       4
#define NT        128
#define BLOCKS_PER_B ((NFRAMES + FPB - 1) / FPB)   // 750
#define NOUTF     1499
#define NOUTF_PAD 1500
#define FEAT_ELEMS (7680000u)
#define MASK_ELEMS (48000u)
#define MAXW 24
#define SPAD(x) ((x) + ((x) >> 3))
#define SLOT_F2 584

// ---- shared layout (floats), phase-overlaid ----
// Region A [0, 1028): sx (880, phase 1) then spow (4*257=1028, phase 2)
// Region B [1028, 3364): sfft 2*584 float2; sfeat 320 overlays (phase 3)
// means [3364, 3368)
#define OFF_A     0
#define OFF_SFFT  1028
#define OFF_MEANS 3364
#define SMEM_FLOATS 3368
#define SMEM_BYTES  (SMEM_FLOATS * 4)    // 13472 B -> 16 blocks/SM (64 warps)

// ---------------- device scratch ---------------------------------------------
__device__ float         g_feats[(size_t)BATCH * NFRAMES * NMEL];
__device__ int           g_melSL[NMEL];               // start | len<<16
__device__ float         g_melWtsT[MAXW * NMEL];
__device__ double        g_sumd [BATCH * NMEL];
__device__ double        g_sumsqd[BATCH * NMEL];
__device__ float         g_stats[BATCH * NMEL * 2];
__device__ unsigned int  g_done;

// ---------------- complex helpers --------------------------------------------
__device__ __forceinline__ float2 cadd(float2 a, float2 b){ return make_float2(a.x+b.x, a.y+b.y); }
__device__ __forceinline__ float2 csub(float2 a, float2 b){ return make_float2(a.x-b.x, a.y-b.y); }
__device__ __forceinline__ float2 cmul(float2 a, float2 b){ return make_float2(a.x*b.x - a.y*b.y, a.x*b.y + a.y*b.x); }
__device__ __forceinline__ float2 crot(float2 a){ return make_float2(a.y, -a.x); }
__device__ __forceinline__ float2 cw1 (float2 a){ const float c=0.70710678118654752f; return make_float2(c*(a.x+a.y), c*(a.y-a.x)); }
__device__ __forceinline__ float2 cw3 (float2 a){ const float c=0.70710678118654752f; return make_float2(c*(a.y-a.x), -c*(a.x+a.y)); }

__device__ __forceinline__ void dft8(float2* x) {
    float2 b0=x[0], b1=x[4], b2=x[2], b3=x[6], b4=x[1], b5=x[5], b6=x[3], b7=x[7];
    float2 c0=cadd(b0,b1), c1=csub(b0,b1), c2=cadd(b2,b3), c3=csub(b2,b3);
    float2 c4=cadd(b4,b5), c5=csub(b4,b5), c6=cadd(b6,b7), c7=csub(b6,b7);
    float2 r3=crot(c3),  r7=crot(c7);
    float2 d0=cadd(c0,c2), d2=csub(c0,c2), d1=cadd(c1,r3), d3=csub(c1,r3);
    float2 d4=cadd(c4,c6), d6=csub(c4,c6), d5=cadd(c5,r7), d7=csub(c5,r7);
    float2 w5=cw1(d5), r6=crot(d6), w7=cw3(d7);
    x[0]=cadd(d0,d4); x[1]=cadd(d1,w5); x[2]=cadd(d2,r6); x[3]=cadd(d3,w7);
    x[4]=csub(d0,d4); x[5]=csub(d1,w5); x[6]=csub(d2,r6); x[7]=csub(d3,w7);
}

__device__ __forceinline__ void twiddle7(float2* x, float pOverL) {
    float s1, c1;
    __sincosf(-6.283185307179586f * pOverL, &s1, &c1);
    const float2 w1 = make_float2(c1, s1);
    float2 w = w1;
    x[1] = cmul(x[1], w);
#pragma unroll
    for (int j = 2; j < 8; j++) { w = cmul(w, w1); x[j] = cmul(x[j], w); }
}

// ---------------- init: one block per mel; block 0 zeroes accumulators -------
__global__ void k_build_table(const float* __restrict__ mf) {
    const int m   = blockIdx.x;
    const int tid = threadIdx.x;
    if (m == 0) {
        for (int i = tid; i < BATCH * NMEL; i += 256) {
            g_sumd[i]   = 0.0;
            g_sumsqd[i] = 0.0;
        }
        if (tid == 0) g_done = 0u;
    }
    __shared__ int s_min, s_max;
    if (tid == 0) { s_min = NBINS; s_max = -1; }
    __syncthreads();
    for (int k = tid; k < NBINS; k += 256) {
        if (mf[k * NMEL + m] != 0.0f) {
            atomicMin(&s_min, k);
            atomicMax(&s_max, k);
        }
    }
    __syncthreads();
    int start = s_min, last = s_max;
    if (last < 0) { start = 0; last = -1; }
    int len = last - start + 1;
    if (len > MAXW) len = MAXW;
    if (len < 0) len = 0;
    if (tid == 0) g_melSL[m] = start | (len << 16);
    if (tid < MAXW)
        g_melWtsT[tid * NMEL + m] = (tid < len) ? mf[(start + tid) * NMEL + m] : 0.0f;
}

// ---------------- K1: 128 threads, 2 FFT slots, 16 blocks/SM ------------------
__global__ __launch_bounds__(NT, 16) void k_frames(
    const float* __restrict__ wav,
    const float* __restrict__ mask,
    const float* __restrict__ window)
{
    extern __shared__ float smemf[];
    float*  sx    = smemf + OFF_A;                    // phase 1
    float*  spow  = smemf + OFF_A;                    // phase 2 (sx dead)
    float2* sfftA = (float2*)(smemf + OFF_SFFT);
    float*  sfeat = smemf + OFF_SFFT;                 // phase 3 (sfft dead)
    float*  smeans= smemf + OFF_MEANS;

    const int tid  = threadIdx.x;
    const int b    = blockIdx.x / BLOCKS_PER_B;
    const int f0   = (blockIdx.x % BLOCKS_PER_B) * FPB;
    const int nf   = min(FPB, NFRAMES - f0);          // 4 or 2 (last); even
    const int npairs = nf >> 1;
    const int nload  = (nf - 1) * HOP + FRAME_LEN;

    const float* wb = wav  + (size_t)b * NSAMP + (size_t)f0 * HOP;
    const float* mb = mask + (size_t)b * NSAMP + (size_t)f0 * HOP;
    for (int i = tid; i < nload; i += NT) sx[i] = __ldcs(&wb[i]) * 32768.0f;
    __syncthreads();

    // ---- per-frame means: warp w handles frame w ----
    {
        const int wid = tid >> 5, lane = tid & 31;
        if (wid < nf) {
            const float* x = sx + wid * HOP;
            float s = 0.f;
            for (int j = lane; j < FRAME_LEN; j += 32) s += x[j];
#pragma unroll
            for (int o = 16; o > 0; o >>= 1) s += __shfl_xor_sync(0xffffffffu, s, o);
            if (lane == 0) smeans[wid] = s * (1.0f / (float)FRAME_LEN);
        }
    }
    __syncthreads();

    const int slot = tid >> 6;                        // 0..1
    const int il   = tid & 63;
    float2* sfft   = sfftA + slot * SLOT_F2;
    const bool act = slot < npairs;

    // ---- stage 0: fused preemph/window/mask + gather + dft8 ----
    if (act) {
        const int fa = slot * 2, fb = fa + 1;
        const float* xa = sx + fa * HOP;
        const float* xb = sx + fb * HOP;
        const float* ga = mb + fa * HOP;
        const float* gb2= mb + fb * HOP;
        const float ca = (1.0f - PREEMPH) * smeans[fa];
        const float cb = (1.0f - PREEMPH) * smeans[fb];
        float2 x[8];
        const int lo = 8 * (il & 7) + (il >> 3);
#pragma unroll
        for (int j = 0; j < 8; j++) {
            const int n = 64 * j + lo;
            if (n < FRAME_LEN) {
                const int nm = n - (n > 0 ? 1 : 0);
                const float wv = __ldg(&window[n]);
                const float va = (xa[n] - PREEMPH * xa[nm] - ca) * wv * __ldcs(&ga[n]);
                const float vb = (xb[n] - PREEMPH * xb[nm] - cb) * wv * __ldcs(&gb2[n]);
                x[j] = make_float2(va, vb);
            } else {
                x[j] = make_float2(0.f, 0.f);
            }
        }
        dft8(x);
        const int base = il * 8;
#pragma unroll
        for (int j = 0; j < 8; j++) sfft[SPAD(base + j)] = x[j];
    }
    __syncthreads();   // all teams done reading sx before spow overlays it

    // ---- stage 1 ----
    if (act) {
        float2 x[8];
        const int p = il & 7, g = il >> 3;
        const int base = g * 64 + p;
#pragma unroll
        for (int j = 0; j < 8; j++) x[j] = sfft[SPAD(base + j * 8)];
        twiddle7(x, (float)p * (1.0f / 64.0f));
        dft8(x);
#pragma unroll
        for (int j = 0; j < 8; j++) sfft[SPAD(base + j * 8)] = x[j];
    }
    __syncthreads();

    // ---- stage 2 ----
    if (act) {
        float2 x[8];
        const int p = il;
#pragma unroll
        for (int j = 0; j < 8; j++) x[j] = sfft[SPAD(p + j * 64)];
        twiddle7(x, (float)p * (1.0f / 512.0f));
        dft8(x);
#pragma unroll
        for (int j = 0; j < 8; j++) sfft[SPAD(p + j * 64)] = x[j];
    }
    __syncthreads();

    // ---- unpack packed real pair -> power spectra (spow overlays dead sx) ----
    for (int idx = tid; idx < 2 * NBINS; idx += NT) {
        const int s = idx / NBINS, k = idx - s * NBINS;
        if (s < npairs) {
            const float2* sf = sfftA + s * SLOT_F2;
            const float2 Z  = sf[SPAD(k)];
            const float2 Zn = sf[SPAD((NFFT - k) & (NFFT - 1))];
            const float ar = Z.x + Zn.x, ai = Z.y - Zn.y;
            const float br = Z.y + Zn.y, bi = Zn.x - Z.x;
            spow[(s * 2 + 0) * NBINS + k] = 0.25f * (ar * ar + ai * ai);
            spow[(s * 2 + 1) * NBINS + k] = 0.25f * (br * br + bi * bi);
        }
    }
    __syncthreads();

    // ---- CSR mel projection + log (sfeat overlays dead sfft) ----
    for (int ch = tid; ch < FPB * NMEL; ch += NT) {
        const int s  = ch / (2 * NMEL);
        const int r  = ch - s * (2 * NMEL);
        const int fr = r / NMEL;
        const int m  = r - fr * NMEL;
        float v = 0.0f;
        if (s < npairs) {
            const int sl = __ldg(&g_melSL[m]);
            const int st = sl & 0xffff;
            const int ln = sl >> 16;
            const float* pw = spow + (s * 2 + fr) * NBINS + st;
            float acc = 0.f;
#pragma unroll 4
            for (int t = 0; t < ln; t++) acc += pw[t] * __ldg(&g_melWtsT[t * NMEL + m]);
            v = __logf(fmaxf(acc, MEL_FLOOR));
            const int frame = f0 + s * 2 + fr;
            g_feats[((size_t)(b * NFRAMES + frame)) * NMEL + m] = v;
        }
        sfeat[ch] = v;     // ch == (s*2+fr)*80 + m
    }
    __syncthreads();

    // ---- block-level stats + double atomics (160/block) ----
    if (tid < NMEL) {
        float s = 0.f, ss = 0.f;
#pragma unroll
        for (int r = 0; r < FPB; r++) {
            const float v = sfeat[r * NMEL + tid];
            s  += v;
            ss += v * v;
        }
        atomicAdd(&g_sumd  [b * NMEL + tid], (double)s);
        atomicAdd(&g_sumsqd[b * NMEL + tid], (double)ss);
    }

    // ---- last block finalizes mean/invstd ----
    __shared__ int s_last;
    __syncthreads();
    if (tid == 0) {
        __threadfence();
        const unsigned int old = atomicAdd(&g_done, 1u);
        s_last = (old == (unsigned int)(gridDim.x - 1));
    }
    __syncthreads();
    if (s_last) {
        for (int i = tid; i < BATCH * NMEL; i += NT) {
            const double S  = __ldcg(&g_sumd[i]);
            const double SS = __ldcg(&g_sumsqd[i]);
            const double F    = (double)NFRAMES;
            const double mean = S / F;
            const double var  = (SS - S * S / F) / (F - 1.0);
            g_stats[i * 2]     = (float)mean;
            g_stats[i * 2 + 1] = (float)(1.0 / sqrt(var + 1e-7));
        }
    }
}

// ---------------- K3: single vectorized output kernel (feat + mask) ----------
__global__ void k_output(float4* __restrict__ out, unsigned nq) {
    const unsigned q = blockIdx.x * blockDim.x + threadIdx.x;
    if (q >= nq) return;
    const unsigned idx = q * 4u;
    float4 o;
    if (idx < FEAT_ELEMS) {
        const unsigned PER_B = (unsigned)NOUTF_PAD * 160u;
        const unsigned b  = idx / PER_B;
        const unsigned r  = idx % PER_B;
        const unsigned f2 = r / 160u;
        const unsigned c  = r % 160u;
        const unsigned fr = 2u * f2 + (c >= 80u ? 1u : 0u);
        const unsigned mel = (c >= 80u) ? (c - 80u) : c;
        if (fr >= NFRAMES) {
            o = make_float4(1.f, 1.f, 1.f, 1.f);
        } else {
            const float* fv = &g_feats[((size_t)(b * NFRAMES + fr)) * NMEL + mel];
            const float* st = &g_stats[(b * NMEL + mel) * 2];
            o.x = (fv[0] - st[0]) * st[1];
            o.y = (fv[1] - st[2]) * st[3];
            o.z = (fv[2] - st[4]) * st[5];
            o.w = (fv[3] - st[6]) * st[7];
        }
    } else {
        const unsigned j0 = idx - FEAT_ELEMS;
        float v[4];
#pragma unroll
        for (int e = 0; e < 4; e++) {
            const unsigned j = j0 + e;
            v[e] = (j < MASK_ELEMS && (j % NOUTF_PAD) < NOUTF) ? 1.0f : 0.0f;
        }
        o = make_float4(v[0], v[1], v[2], v[3]);
    }
    out[q] = o;
}

__global__ void k_output_tail(float* __restrict__ out, size_t start, size_t out_size) {
    const size_t idx = start + (size_t)blockIdx.x * blockDim.x + threadIdx.x;
    if (idx >= out_size) return;
    float v = 0.0f;
    if (idx >= FEAT_ELEMS) {
        const size_t j = idx - FEAT_ELEMS;
        v = (j < MASK_ELEMS && (int)(j % NOUTF_PAD) < NOUTF) ? 1.0f : 0.0f;
    }
    out[idx] = v;
}

// ---------------- launch -----------------------------------------------------
extern "C" void kernel_launch(void* const* d_in, const int* in_sizes, int n_in,
                              void* d_out, int out_size) {
    const float* raw    = (const float*)d_in[0];
    const float* mask   = (const float*)d_in[1];
    const float* melf   = (const float*)d_in[2];
    const float* window = (const float*)d_in[3];
    float*       out    = (float*)d_out;

    cudaFuncSetAttribute(k_frames, cudaFuncAttributeMaxDynamicSharedMemorySize, SMEM_BYTES);

    k_build_table<<<NMEL, 256>>>(melf);
    k_frames<<<BATCH * BLOCKS_PER_B, NT, SMEM_BYTES>>>(raw, mask, window);
    const size_t os = (size_t)out_size;
    const unsigned nq = (unsigned)(os / 4);
    k_output<<<(nq + 255) / 256, 256>>>((float4*)out, nq);
    if (os & 3) {
        k_output_tail<<<1, 256>>>(out, (size_t)nq * 4, os);
    }
}

// round 17
// speedup vs baseline: 1.1617x; 1.1617x over previous
#include <cuda_runtime.h>
#include <math.h>
#include <stdint.h>

#define FRAME_LEN 400
#define HOP       160
#define NFFT      512
#define NBINS     257
#define NMEL      80
#define NFRAMES   2998
#define NSAMP     480000
#define BATCH     32
#define PREEMPH   0.97f
#define MEL_FLOOR 1.192092955078125e-07f
#define FPB       8
#define BLOCKS_PER_B ((NFRAMES + FPB - 1) / FPB)   // 375
#define NOUTF     1499
#define NOUTF_PAD 1500
#define FEAT_ELEMS (7680000u)                       // 32*1500*160
#define MASK_ELEMS (48000u)                         // 32*1500
#define MAXW 24
#define SPAD(x) ((x) + ((x) >> 3))
#define SLOT_F2 584

// ---- shared layout (floats), phase-overlaid (R10/R15 structure) ----
// Region A [0, 2056): sx (1520, phase 1) then spow (2056, phase 2)
// Region B [2056, 6728): sfft 4*584 float2 (phase 1-2) then sfeat 640 (phase 3)
// means [6728, 6736)
#define OFF_A     0
#define OFF_SFFT  2056
#define OFF_MEANS 6728
#define SMEM_FLOATS 6736
#define SMEM_BYTES  (SMEM_FLOATS * 4)    // 26944 B -> 8 blocks/SM (64 warps)

// ---------------- device scratch ---------------------------------------------
__device__ float         g_feats[(size_t)BATCH * NFRAMES * NMEL];
__device__ int           g_melStart[NMEL];
__device__ int           g_melLen[NMEL];
__device__ float         g_melWtsT[MAXW * NMEL];
__device__ double        g_sumd [BATCH * NMEL];
__device__ double        g_sumsqd[BATCH * NMEL];
__device__ float         g_stats[BATCH * NMEL * 2];
__device__ unsigned int  g_done;

// ---------------- complex helpers --------------------------------------------
__device__ __forceinline__ float2 cadd(float2 a, float2 b){ return make_float2(a.x+b.x, a.y+b.y); }
__device__ __forceinline__ float2 csub(float2 a, float2 b){ return make_float2(a.x-b.x, a.y-b.y); }
__device__ __forceinline__ float2 cmul(float2 a, float2 b){ return make_float2(a.x*b.x - a.y*b.y, a.x*b.y + a.y*b.x); }
__device__ __forceinline__ float2 crot(float2 a){ return make_float2(a.y, -a.x); }
__device__ __forceinline__ float2 cw1 (float2 a){ const float c=0.70710678118654752f; return make_float2(c*(a.x+a.y), c*(a.y-a.x)); }
__device__ __forceinline__ float2 cw3 (float2 a){ const float c=0.70710678118654752f; return make_float2(c*(a.y-a.x), -c*(a.x+a.y)); }

__device__ __forceinline__ void dft8(float2* x) {
    float2 b0=x[0], b1=x[4], b2=x[2], b3=x[6], b4=x[1], b5=x[5], b6=x[3], b7=x[7];
    float2 c0=cadd(b0,b1), c1=csub(b0,b1), c2=cadd(b2,b3), c3=csub(b2,b3);
    float2 c4=cadd(b4,b5), c5=csub(b4,b5), c6=cadd(b6,b7), c7=csub(b6,b7);
    float2 r3=crot(c3),  r7=crot(c7);
    float2 d0=cadd(c0,c2), d2=csub(c0,c2), d1=cadd(c1,r3), d3=csub(c1,r3);
    float2 d4=cadd(c4,c6), d6=csub(c4,c6), d5=cadd(c5,r7), d7=csub(c5,r7);
    float2 w5=cw1(d5), r6=crot(d6), w7=cw3(d7);
    x[0]=cadd(d0,d4); x[1]=cadd(d1,w5); x[2]=cadd(d2,r6); x[3]=cadd(d3,w7);
    x[4]=csub(d0,d4); x[5]=csub(d1,w5); x[6]=csub(d2,r6); x[7]=csub(d3,w7);
}

__device__ __forceinline__ void twiddle7(float2* x, float pOverL) {
    float s1, c1;
    __sincosf(-6.283185307179586f * pOverL, &s1, &c1);
    const float2 w1 = make_float2(c1, s1);
    float2 w = w1;
    x[1] = cmul(x[1], w);
#pragma unroll
    for (int j = 2; j < 8; j++) { w = cmul(w, w1); x[j] = cmul(x[j], w); }
}

// ---------------- init: one block per mel; block 0 zeroes accumulators -------
__global__ void k_build_table(const float* __restrict__ mf) {
    const int m   = blockIdx.x;
    const int tid = threadIdx.x;
    if (m == 0) {
        for (int i = tid; i < BATCH * NMEL; i += 256) {
            g_sumd[i]   = 0.0;
            g_sumsqd[i] = 0.0;
        }
        if (tid == 0) g_done = 0u;
    }
    __shared__ int s_min, s_max;
    if (tid == 0) { s_min = NBINS; s_max = -1; }
    __syncthreads();
    for (int k = tid; k < NBINS; k += 256) {
        if (mf[k * NMEL + m] != 0.0f) {
            atomicMin(&s_min, k);
            atomicMax(&s_max, k);
        }
    }
    __syncthreads();
    int start = s_min, last = s_max;
    if (last < 0) { start = 0; last = -1; }
    int len = last - start + 1;
    if (len > MAXW) len = MAXW;
    if (tid == 0) { g_melStart[m] = start; g_melLen[m] = len; }
    if (tid < MAXW)
        g_melWtsT[tid * NMEL + m] = (tid < len) ? mf[(start + tid) * NMEL + m] : 0.0f;
}

// ---------------- K1 (final: R10 structure + streaming hints) ----------------
__global__ __launch_bounds__(256, 8) void k_frames(
    const float* __restrict__ wav,
    const float* __restrict__ mask,
    const float* __restrict__ window)
{
    extern __shared__ float smemf[];
    float*  sx    = smemf + OFF_A;                    // phase 1
    float*  spow  = smemf + OFF_A;                    // phase 2 (sx dead)
    float2* sfftA = (float2*)(smemf + OFF_SFFT);
    float*  sfeat = smemf + OFF_SFFT;                 // phase 3 (sfft dead)
    float*  smeans= smemf + OFF_MEANS;

    const int tid  = threadIdx.x;
    const int b    = blockIdx.x / BLOCKS_PER_B;
    const int f0   = (blockIdx.x % BLOCKS_PER_B) * FPB;
    const int nf   = min(FPB, NFRAMES - f0);
    const int npairs = nf >> 1;
    const int nload  = (nf - 1) * HOP + FRAME_LEN;

    const float* wb = wav  + (size_t)b * NSAMP + (size_t)f0 * HOP;
    const float* mb = mask + (size_t)b * NSAMP + (size_t)f0 * HOP;
    for (int i = tid; i < nload; i += 256) sx[i] = __ldcs(&wb[i]) * 32768.0f;
    __syncthreads();

    // ---- per-frame means ----
    {
        const int wid = tid >> 5, lane = tid & 31;
        if (wid < nf) {
            const float* x = sx + wid * HOP;
            float s = 0.f;
            for (int j = lane; j < FRAME_LEN; j += 32) s += x[j];
#pragma unroll
            for (int o = 16; o > 0; o >>= 1) s += __shfl_xor_sync(0xffffffffu, s, o);
            if (lane == 0) smeans[wid] = s * (1.0f / (float)FRAME_LEN);
        }
    }
    __syncthreads();

    const int slot = tid >> 6;
    const int il   = tid & 63;
    float2* sfft   = sfftA + slot * SLOT_F2;
    const bool act = slot < npairs;

    // ---- stage 0: fused preemph/window(L1)/mask(streaming) + gather + dft8 ----
    if (act) {
        const int fa = slot * 2, fb = fa + 1;
        const float* xa = sx + fa * HOP;
        const float* xb = sx + fb * HOP;
        const float* ga = mb + fa * HOP;
        const float* gb2= mb + fb * HOP;
        const float ca = (1.0f - PREEMPH) * smeans[fa];
        const float cb = (1.0f - PREEMPH) * smeans[fb];
        float2 x[8];
        const int lo = 8 * (il & 7) + (il >> 3);
#pragma unroll
        for (int j = 0; j < 8; j++) {
            const int n = 64 * j + lo;
            if (n < FRAME_LEN) {
                const int nm = n - (n > 0 ? 1 : 0);
                const float wv = __ldg(&window[n]);
                const float va = (xa[n] - PREEMPH * xa[nm] - ca) * wv * __ldcs(&ga[n]);
                const float vb = (xb[n] - PREEMPH * xb[nm] - cb) * wv * __ldcs(&gb2[n]);
                x[j] = make_float2(va, vb);
            } else {
                x[j] = make_float2(0.f, 0.f);
            }
        }
        dft8(x);
        const int base = il * 8;
#pragma unroll
        for (int j = 0; j < 8; j++) sfft[SPAD(base + j)] = x[j];
    }
    __syncthreads();

    // ---- stage 1 ----
    if (act) {
        float2 x[8];
        const int p = il & 7, g = il >> 3;
        const int base = g * 64 + p;
#pragma unroll
        for (int j = 0; j < 8; j++) x[j] = sfft[SPAD(base + j * 8)];
        twiddle7(x, (float)p * (1.0f / 64.0f));
        dft8(x);
#pragma unroll
        for (int j = 0; j < 8; j++) sfft[SPAD(base + j * 8)] = x[j];
    }
    __syncthreads();

    // ---- stage 2 ----
    if (act) {
        float2 x[8];
        const int p = il;
#pragma unroll
        for (int j = 0; j < 8; j++) x[j] = sfft[SPAD(p + j * 64)];
        twiddle7(x, (float)p * (1.0f / 512.0f));
        dft8(x);
#pragma unroll
        for (int j = 0; j < 8; j++) sfft[SPAD(p + j * 64)] = x[j];
    }
    __syncthreads();

    // ---- unpack packed real pair -> power spectra (spow overlays dead sx) ----
    for (int idx = tid; idx < 4 * NBINS; idx += 256) {
        const int s = idx / NBINS, k = idx - s * NBINS;
        if (s < npairs) {
            const float2* sf = sfftA + s * SLOT_F2;
            const float2 Z  = sf[SPAD(k)];
            const float2 Zn = sf[SPAD((NFFT - k) & (NFFT - 1))];
            const float ar = Z.x + Zn.x, ai = Z.y - Zn.y;
            const float br = Z.y + Zn.y, bi = Zn.x - Z.x;
            spow[(s * 2 + 0) * NBINS + k] = 0.25f * (ar * ar + ai * ai);
            spow[(s * 2 + 1) * NBINS + k] = 0.25f * (br * br + bi * bi);
        }
    }
    __syncthreads();

    // ---- CSR mel projection + log (sfeat overlays dead sfft) ----
    for (int ch = tid; ch < 4 * 2 * NMEL; ch += 256) {
        const int s  = ch / (2 * NMEL);
        const int r  = ch - s * (2 * NMEL);
        const int fr = r / NMEL;
        const int m  = r - fr * NMEL;
        float v = 0.0f;
        if (s < npairs) {
            const int st = __ldg(&g_melStart[m]);
            const int ln = __ldg(&g_melLen[m]);
            const float* pw = spow + (s * 2 + fr) * NBINS + st;
            float acc = 0.f;
#pragma unroll 4
            for (int t = 0; t < ln; t++) acc += pw[t] * __ldg(&g_melWtsT[t * NMEL + m]);
            v = __logf(fmaxf(acc, MEL_FLOOR));
            const int frame = f0 + s * 2 + fr;
            g_feats[((size_t)(b * NFRAMES + frame)) * NMEL + m] = v;
        }
        sfeat[ch] = v;
    }
    __syncthreads();

    // ---- block-level stats + double atomics ----
    if (tid < NMEL) {
        float s = 0.f, ss = 0.f;
#pragma unroll
        for (int r = 0; r < FPB; r++) {
            const float v = sfeat[r * NMEL + tid];
            s  += v;
            ss += v * v;
        }
        atomicAdd(&g_sumd  [b * NMEL + tid], (double)s);
        atomicAdd(&g_sumsqd[b * NMEL + tid], (double)ss);
    }

    // ---- last block finalizes mean/invstd ----
    __shared__ int s_last;
    __syncthreads();
    if (tid == 0) {
        __threadfence();
        const unsigned int old = atomicAdd(&g_done, 1u);
        s_last = (old == (unsigned int)(gridDim.x - 1));
    }
    __syncthreads();
    if (s_last) {
        for (int i = tid; i < BATCH * NMEL; i += 256) {
            const double S  = __ldcg(&g_sumd[i]);
            const double SS = __ldcg(&g_sumsqd[i]);
            const double F    = (double)NFRAMES;
            const double mean = S / F;
            const double var  = (SS - S * S / F) / (F - 1.0);
            g_stats[i * 2]     = (float)mean;
            g_stats[i * 2 + 1] = (float)(1.0 / sqrt(var + 1e-7));
        }
    }
}

// ---------------- K3: single vectorized output kernel (feat + mask) ----------
__global__ void k_output(float4* __restrict__ out, unsigned nq) {
    const unsigned q = blockIdx.x * blockDim.x + threadIdx.x;
    if (q >= nq) return;
    const unsigned idx = q * 4u;
    float4 o;
    if (idx < FEAT_ELEMS) {
        const unsigned PER_B = (unsigned)NOUTF_PAD * 160u;
        const unsigned b  = idx / PER_B;
        const unsigned r  = idx % PER_B;
        const unsigned f2 = r / 160u;
        const unsigned c  = r % 160u;
        const unsigned fr = 2u * f2 + (c >= 80u ? 1u : 0u);
        const unsigned mel = (c >= 80u) ? (c - 80u) : c;
        if (fr >= NFRAMES) {
            o = make_float4(1.f, 1.f, 1.f, 1.f);
        } else {
            const float* fv = &g_feats[((size_t)(b * NFRAMES + fr)) * NMEL + mel];
            const float* st = &g_stats[(b * NMEL + mel) * 2];
            o.x = (fv[0] - st[0]) * st[1];
            o.y = (fv[1] - st[2]) * st[3];
            o.z = (fv[2] - st[4]) * st[5];
            o.w = (fv[3] - st[6]) * st[7];
        }
    } else {
        const unsigned j0 = idx - FEAT_ELEMS;
        float v[4];
#pragma unroll
        for (int e = 0; e < 4; e++) {
            const unsigned j = j0 + e;
            v[e] = (j < MASK_ELEMS && (j % NOUTF_PAD) < NOUTF) ? 1.0f : 0.0f;
        }
        o = make_float4(v[0], v[1], v[2], v[3]);
    }
    out[q] = o;
}

__global__ void k_output_tail(float* __restrict__ out, size_t start, size_t out_size) {
    const size_t idx = start + (size_t)blockIdx.x * blockDim.x + threadIdx.x;
    if (idx >= out_size) return;
    float v = 0.0f;
    if (idx >= FEAT_ELEMS) {
        const size_t j = idx - FEAT_ELEMS;
        v = (j < MASK_ELEMS && (int)(j % NOUTF_PAD) < NOUTF) ? 1.0f : 0.0f;
    }
    out[idx] = v;
}

// ---------------- launch -----------------------------------------------------
extern "C" void kernel_launch(void* const* d_in, const int* in_sizes, int n_in,
                              void* d_out, int out_size) {
    const float* raw    = (const float*)d_in[0];
    const float* mask   = (const float*)d_in[1];
    const float* melf   = (const float*)d_in[2];
    const float* window = (const float*)d_in[3];
    float*       out    = (float*)d_out;

    cudaFuncSetAttribute(k_frames, cudaFuncAttributeMaxDynamicSharedMemorySize, SMEM_BYTES);

    k_build_table<<<NMEL, 256>>>(melf);
    k_frames<<<BATCH * BLOCKS_PER_B, 256, SMEM_BYTES>>>(raw, mask, window);
    const size_t os = (size_t)out_size;
    const unsigned nq = (unsigned)(os / 4);
    k_output<<<(nq + 255) / 256, 256>>>((float4*)out, nq);
    if (os & 3) {
        k_output_tail<<<1, 256>>>(out, (size_t)nq * 4, os);
    }
}